// round 11
// baseline (speedup 1.0000x reference)
#include <cuda_runtime.h>
#include <cuda_fp16.h>
#include <cstdint>

#define NNODES 10000
#define INF 128
#define OUTF 256
#define CAP 160

// Scratch (device globals — no allocations allowed). g_cnt zero at load;
// gather re-zeroes it every call, so fill always starts from zeros.
__device__ __align__(16) __half g_h16[NNODES * INF];   // gathered h, fp16
__device__ __align__(16) __half g_f16[NNODES * INF];   // feature, fp16
__device__ __align__(16) __half g_W16[INF * OUTF];     // W, fp16
__device__ int g_cnt[NNODES];
__device__ int g_col[NNODES * CAP];

// ---------------------------------------------------------------------------
// 1) frontend: blocks [0,FILL_B) = bucket fill; blocks [FILL_B,...) = prep.
//    fill (ATOMG latency-bound) and prep (BW-bound) overlap on the SMs.
// ---------------------------------------------------------------------------
#define FILL_B 625

__global__ void __launch_bounds__(256) frontend_kernel(
    const float* __restrict__ feature, const float* __restrict__ W,
    const int* __restrict__ src, const int* __restrict__ dst, int n_edges)
{
    if (blockIdx.x < FILL_B) {
        // ---- fill: 4 edges/thread, 4 independent atomic chains ----
        int t = blockIdx.x * blockDim.x + threadIdx.x;
        int e0 = t * 4;
        if (e0 + 4 <= n_edges) {
            int4 d4 = __ldg(reinterpret_cast<const int4*>(dst) + t);
            int4 s4 = __ldg(reinterpret_cast<const int4*>(src) + t);
            int p0 = atomicAdd(&g_cnt[d4.x], 1);
            int p1 = atomicAdd(&g_cnt[d4.y], 1);
            int p2 = atomicAdd(&g_cnt[d4.z], 1);
            int p3 = atomicAdd(&g_cnt[d4.w], 1);
            if (p0 < CAP) g_col[d4.x * CAP + p0] = s4.x;
            if (p1 < CAP) g_col[d4.y * CAP + p1] = s4.y;
            if (p2 < CAP) g_col[d4.z * CAP + p2] = s4.z;
            if (p3 < CAP) g_col[d4.w * CAP + p3] = s4.w;
        } else {
            for (int e = e0; e < n_edges; e++) {
                int d = __ldg(dst + e);
                int s = __ldg(src + e);
                int p = atomicAdd(&g_cnt[d], 1);
                if (p < CAP) g_col[d * CAP + p] = s;
            }
        }
    } else {
        // ---- prep: feature f32->f16 (8/thread), W f32->f16 ----
        int i = (blockIdx.x - FILL_B) * blockDim.x + threadIdx.x;
        const int NCONV = NNODES * INF / 8;   // 160000
        if (i < NCONV) {
            float4 a = __ldg(reinterpret_cast<const float4*>(feature) + i * 2);
            float4 b = __ldg(reinterpret_cast<const float4*>(feature) + i * 2 + 1);
            __half2 h0 = __floats2half2_rn(a.x, a.y);
            __half2 h1 = __floats2half2_rn(a.z, a.w);
            __half2 h2 = __floats2half2_rn(b.x, b.y);
            __half2 h3 = __floats2half2_rn(b.z, b.w);
            uint4 o;
            o.x = *reinterpret_cast<uint32_t*>(&h0);
            o.y = *reinterpret_cast<uint32_t*>(&h1);
            o.z = *reinterpret_cast<uint32_t*>(&h2);
            o.w = *reinterpret_cast<uint32_t*>(&h3);
            reinterpret_cast<uint4*>(g_f16)[i] = o;
        }
        if (i < INF * OUTF / 8) {   // 4096 threads convert W
            float4 a = __ldg(reinterpret_cast<const float4*>(W) + i * 2);
            float4 b = __ldg(reinterpret_cast<const float4*>(W) + i * 2 + 1);
            __half2 h0 = __floats2half2_rn(a.x, a.y);
            __half2 h1 = __floats2half2_rn(a.z, a.w);
            __half2 h2 = __floats2half2_rn(b.x, b.y);
            __half2 h3 = __floats2half2_rn(b.z, b.w);
            uint4 o;
            o.x = *reinterpret_cast<uint32_t*>(&h0);
            o.y = *reinterpret_cast<uint32_t*>(&h1);
            o.z = *reinterpret_cast<uint32_t*>(&h2);
            o.w = *reinterpret_cast<uint32_t*>(&h3);
            reinterpret_cast<uint4*>(g_W16)[i] = o;
        }
    }
}

// ---------------------------------------------------------------------------
// 2) gather (fp16 rows): one warp per node; fp32 accumulate; write fp16 h row.
//    Re-zeroes g_cnt[node] so the next kernel_launch's fill starts clean.
// ---------------------------------------------------------------------------
__device__ __forceinline__ void acc_half4(float4& acc, uint2 v) {
    float2 lo = __half22float2(*reinterpret_cast<__half2*>(&v.x));
    float2 hi = __half22float2(*reinterpret_cast<__half2*>(&v.y));
    acc.x += lo.x; acc.y += lo.y; acc.z += hi.x; acc.w += hi.y;
}

__global__ void __launch_bounds__(256) gather_kernel() {
    int node = (blockIdx.x * blockDim.x + threadIdx.x) >> 5;
    int lane = threadIdx.x & 31;
    if (node >= NNODES) return;

    int cnt = g_cnt[node];
    if (lane == 0) g_cnt[node] = 0;   // reset for the next kernel_launch call
    if (cnt > CAP) cnt = CAP;
    const int* col = g_col + node * CAP;
    const uint2* f = reinterpret_cast<const uint2*>(g_f16);

    float4 acc = make_float4(0.f, 0.f, 0.f, 0.f);
    int j = 0;
    for (; j + 32 <= cnt; j += 32) {
        int idx = __ldg(col + j + lane);
#pragma unroll
        for (int k = 0; k < 32; k += 8) {
            int s0 = __shfl_sync(0xffffffffu, idx, k);
            int s1 = __shfl_sync(0xffffffffu, idx, k + 1);
            int s2 = __shfl_sync(0xffffffffu, idx, k + 2);
            int s3 = __shfl_sync(0xffffffffu, idx, k + 3);
            int s4 = __shfl_sync(0xffffffffu, idx, k + 4);
            int s5 = __shfl_sync(0xffffffffu, idx, k + 5);
            int s6 = __shfl_sync(0xffffffffu, idx, k + 6);
            int s7 = __shfl_sync(0xffffffffu, idx, k + 7);
            uint2 v0 = __ldg(f + s0 * 32 + lane);
            uint2 v1 = __ldg(f + s1 * 32 + lane);
            uint2 v2 = __ldg(f + s2 * 32 + lane);
            uint2 v3 = __ldg(f + s3 * 32 + lane);
            uint2 v4 = __ldg(f + s4 * 32 + lane);
            uint2 v5 = __ldg(f + s5 * 32 + lane);
            uint2 v6 = __ldg(f + s6 * 32 + lane);
            uint2 v7 = __ldg(f + s7 * 32 + lane);
            acc_half4(acc, v0); acc_half4(acc, v1);
            acc_half4(acc, v2); acc_half4(acc, v3);
            acc_half4(acc, v4); acc_half4(acc, v5);
            acc_half4(acc, v6); acc_half4(acc, v7);
        }
    }
    if (j < cnt) {
        int rem = cnt - j;
        int idx = (lane < rem) ? __ldg(col + j + lane) : 0;
        for (int k = 0; k < rem; k++) {
            int s = __shfl_sync(0xffffffffu, idx, k);
            uint2 v = __ldg(f + s * 32 + lane);
            acc_half4(acc, v);
        }
    }
    __half2 h01 = __floats2half2_rn(acc.x, acc.y);
    __half2 h23 = __floats2half2_rn(acc.z, acc.w);
    uint2 o;
    o.x = *reinterpret_cast<uint32_t*>(&h01);
    o.y = *reinterpret_cast<uint32_t*>(&h23);
    reinterpret_cast<uint2*>(g_h16)[node * 32 + lane] = o;
}

// ---------------------------------------------------------------------------
// 3) out = h @ W + b. fp16 mma m16n8k16, fp32 accum, ldmatrix fragments.
//    Block tile 128(M)x64(N), KC=32, 3-stage cp.async ring, one sync/iter.
//    Final iteration uses wait_group 0 (round-9 race fix — load-bearing).
// ---------------------------------------------------------------------------
#define KC 32
#define SA_STR 40
#define SB_STR 72
#define NITER (INF / KC)

__device__ __forceinline__ void cpa16(uint32_t dst, const void* src, int sz) {
    asm volatile("cp.async.cg.shared.global [%0], [%1], 16, %2;"
                 :: "r"(dst), "l"(src), "r"(sz) : "memory");
}
#define LDSM_X4(r0, r1, r2, r3, addr)                                        \
    asm volatile("ldmatrix.sync.aligned.m8n8.x4.shared.b16 {%0,%1,%2,%3}, [%4];" \
                 : "=r"(r0), "=r"(r1), "=r"(r2), "=r"(r3) : "r"(addr))
#define LDSM_X4_T(r0, r1, r2, r3, addr)                                      \
    asm volatile("ldmatrix.sync.aligned.m8n8.x4.trans.shared.b16 {%0,%1,%2,%3}, [%4];" \
                 : "=r"(r0), "=r"(r1), "=r"(r2), "=r"(r3) : "r"(addr))

__global__ void __launch_bounds__(256) gemm_tc_kernel(
    const float* __restrict__ bias,
    float* __restrict__ out)
{
    __shared__ __half sa[3][128 * SA_STR];
    __shared__ __half sb[3][KC * SB_STR];

    int t    = threadIdx.x;
    int warp = t >> 5;
    int lane = t & 31;
    int gid  = lane >> 2;
    int tig  = lane & 3;

    int m0 = blockIdx.x * 128;
    int n0 = blockIdx.y * 64;
    int wm = (warp & 3) * 32;
    int wn = (warp >> 2) * 32;

    uint32_t sa_base = (uint32_t)__cvta_generic_to_shared(&sa[0][0]);
    uint32_t sb_base = (uint32_t)__cvta_generic_to_shared(&sb[0][0]);

    int am[2], ac8[2];
#pragma unroll
    for (int j = 0; j < 2; j++) {
        int slot = t + j * 256;
        am[j]  = slot >> 2;
        ac8[j] = slot & 3;
    }
    int bkr = t >> 3;
    int bc8 = t & 7;

    int a_row = (lane & 15);
    int a_col = (lane >> 4) * 8;
    int b_row = (lane & 15);
    int b_col = (lane >> 4) * 8;

    float c[2][4][4];
#pragma unroll
    for (int mt = 0; mt < 2; mt++)
#pragma unroll
        for (int nt = 0; nt < 4; nt++)
#pragma unroll
            for (int r = 0; r < 4; r++) c[mt][nt][r] = 0.f;

    auto issue = [&](int st, int kc) {
#pragma unroll
        for (int j = 0; j < 2; j++) {
            int gm = m0 + am[j];
            int sz = (gm < NNODES) ? 16 : 0;
            cpa16(sa_base + (uint32_t)((st * 128 * SA_STR + am[j] * SA_STR + ac8[j] * 8) * 2),
                  g_h16 + (size_t)gm * INF + kc + ac8[j] * 8, sz);
        }
        cpa16(sb_base + (uint32_t)((st * KC * SB_STR + bkr * SB_STR + bc8 * 8) * 2),
              g_W16 + (size_t)(kc + bkr) * OUTF + n0 + bc8 * 8, 16);
        asm volatile("cp.async.commit_group;" ::: "memory");
    };

    issue(0, 0);
    issue(1, KC);

#pragma unroll
    for (int it = 0; it < NITER; it++) {
        if (it == NITER - 1)
            asm volatile("cp.async.wait_group 0;" ::: "memory");
        else
            asm volatile("cp.async.wait_group 1;" ::: "memory");
        __syncthreads();
        if (it + 2 < NITER) issue((it + 2) % 3, (it + 2) * KC);

        uint32_t A0 = sa_base + (uint32_t)((it % 3) * 128 * SA_STR * 2);
        uint32_t B0 = sb_base + (uint32_t)((it % 3) * KC * SB_STR * 2);

#pragma unroll
        for (int ks = 0; ks < KC; ks += 16) {
            uint32_t a[2][4];
#pragma unroll
            for (int mt = 0; mt < 2; mt++) {
                uint32_t addr = A0 + (uint32_t)(((wm + mt * 16 + a_row) * SA_STR
                                                 + ks + a_col) * 2);
                LDSM_X4(a[mt][0], a[mt][1], a[mt][2], a[mt][3], addr);
            }
            uint32_t bf[4][2];
#pragma unroll
            for (int np = 0; np < 2; np++) {
                uint32_t r0, r1, r2, r3;
                uint32_t addr = B0 + (uint32_t)(((ks + b_row) * SB_STR
                                                 + wn + np * 16 + b_col) * 2);
                LDSM_X4_T(r0, r1, r2, r3, addr);
                bf[np * 2][0] = r0; bf[np * 2][1] = r1;
                bf[np * 2 + 1][0] = r2; bf[np * 2 + 1][1] = r3;
            }
#pragma unroll
            for (int mt = 0; mt < 2; mt++)
#pragma unroll
                for (int nt = 0; nt < 4; nt++) {
                    asm volatile(
                        "mma.sync.aligned.m16n8k16.row.col.f32.f16.f16.f32 "
                        "{%0,%1,%2,%3}, {%4,%5,%6,%7}, {%8,%9}, {%0,%1,%2,%3};"
                        : "+f"(c[mt][nt][0]), "+f"(c[mt][nt][1]),
                          "+f"(c[mt][nt][2]), "+f"(c[mt][nt][3])
                        : "r"(a[mt][0]), "r"(a[mt][1]), "r"(a[mt][2]), "r"(a[mt][3]),
                          "r"(bf[nt][0]), "r"(bf[nt][1]));
                }
        }
    }

#pragma unroll
    for (int nt = 0; nt < 4; nt++) {
        int colg = n0 + wn + nt * 8 + tig * 2;
        float2 bv = *reinterpret_cast<const float2*>(bias + colg);
#pragma unroll
        for (int mt = 0; mt < 2; mt++) {
            int row0 = m0 + wm + mt * 16 + gid;
            int row1 = row0 + 8;
            if (row0 < NNODES) {
                float2 o = make_float2(c[mt][nt][0] + bv.x, c[mt][nt][1] + bv.y);
                *reinterpret_cast<float2*>(out + (size_t)row0 * OUTF + colg) = o;
            }
            if (row1 < NNODES) {
                float2 o = make_float2(c[mt][nt][2] + bv.x, c[mt][nt][3] + bv.y);
                *reinterpret_cast<float2*>(out + (size_t)row1 * OUTF + colg) = o;
            }
        }
    }
}

// ---------------------------------------------------------------------------
extern "C" void kernel_launch(void* const* d_in, const int* in_sizes, int n_in,
                              void* d_out, int out_size) {
    const float* feature = (const float*)d_in[0];
    const int*   src     = (const int*)d_in[1];
    const int*   dst     = (const int*)d_in[2];
    const float* W       = (const float*)d_in[3];
    const float* b       = (const float*)d_in[4];
    float*       out     = (float*)d_out;

    int n_edges = in_sizes[1];

    frontend_kernel<<<FILL_B + 625, 256>>>(feature, W, src, dst, n_edges);

    int gather_blocks = (NNODES * 32 + 255) / 256;
    gather_kernel<<<gather_blocks, 256>>>();

    dim3 grid((NNODES + 127) / 128, OUTF / 64);
    gemm_tc_kernel<<<grid, 256>>>(b, out);
}

// round 12
// speedup vs baseline: 1.0871x; 1.0871x over previous
#include <cuda_runtime.h>
#include <cuda_fp16.h>
#include <cstdint>

#define NNODES 10000
#define INF 128
#define OUTF 256
#define CAP 160

// Scratch (device globals — no allocations allowed).
__device__ __align__(16) __half g_h16[NNODES * INF];   // gathered h, fp16
__device__ __align__(16) __half g_f16[NNODES * INF];   // feature, fp16
__device__ __align__(16) __half g_W16[INF * OUTF];     // W, fp16
__device__ int g_cnt[NNODES];
__device__ int g_col[NNODES * CAP];

// ---------------------------------------------------------------------------
// 1) prep: feature f32->f16, W f32->f16, zero g_cnt.
// ---------------------------------------------------------------------------
__global__ void __launch_bounds__(256) prep_kernel(
    const float* __restrict__ feature, const float* __restrict__ W) {
    int i = blockIdx.x * blockDim.x + threadIdx.x;
    const int NCONV = NNODES * INF / 8;   // 160000
    if (i < NCONV) {
        float4 a = __ldg(reinterpret_cast<const float4*>(feature) + i * 2);
        float4 b = __ldg(reinterpret_cast<const float4*>(feature) + i * 2 + 1);
        __half2 h0 = __floats2half2_rn(a.x, a.y);
        __half2 h1 = __floats2half2_rn(a.z, a.w);
        __half2 h2 = __floats2half2_rn(b.x, b.y);
        __half2 h3 = __floats2half2_rn(b.z, b.w);
        uint4 o;
        o.x = *reinterpret_cast<uint32_t*>(&h0);
        o.y = *reinterpret_cast<uint32_t*>(&h1);
        o.z = *reinterpret_cast<uint32_t*>(&h2);
        o.w = *reinterpret_cast<uint32_t*>(&h3);
        reinterpret_cast<uint4*>(g_f16)[i] = o;
    }
    if (i < INF * OUTF / 8) {   // 4096 threads convert W
        float4 a = __ldg(reinterpret_cast<const float4*>(W) + i * 2);
        float4 b = __ldg(reinterpret_cast<const float4*>(W) + i * 2 + 1);
        __half2 h0 = __floats2half2_rn(a.x, a.y);
        __half2 h1 = __floats2half2_rn(a.z, a.w);
        __half2 h2 = __floats2half2_rn(b.x, b.y);
        __half2 h3 = __floats2half2_rn(b.z, b.w);
        uint4 o;
        o.x = *reinterpret_cast<uint32_t*>(&h0);
        o.y = *reinterpret_cast<uint32_t*>(&h1);
        o.z = *reinterpret_cast<uint32_t*>(&h2);
        o.w = *reinterpret_cast<uint32_t*>(&h3);
        reinterpret_cast<uint4*>(g_W16)[i] = o;
    }
    if (i < NNODES) g_cnt[i] = 0;
}

// ---------------------------------------------------------------------------
// 2) bucket fill: 4 edges per thread (int4 loads, 4 independent atomic chains)
// ---------------------------------------------------------------------------
__global__ void __launch_bounds__(256) fill_kernel(
    const int* __restrict__ src, const int* __restrict__ dst, int n_edges) {
    int t = blockIdx.x * blockDim.x + threadIdx.x;
    int e0 = t * 4;
    if (e0 + 4 <= n_edges) {
        int4 d4 = __ldg(reinterpret_cast<const int4*>(dst) + t);
        int4 s4 = __ldg(reinterpret_cast<const int4*>(src) + t);
        int p0 = atomicAdd(&g_cnt[d4.x], 1);
        int p1 = atomicAdd(&g_cnt[d4.y], 1);
        int p2 = atomicAdd(&g_cnt[d4.z], 1);
        int p3 = atomicAdd(&g_cnt[d4.w], 1);
        if (p0 < CAP) g_col[d4.x * CAP + p0] = s4.x;
        if (p1 < CAP) g_col[d4.y * CAP + p1] = s4.y;
        if (p2 < CAP) g_col[d4.z * CAP + p2] = s4.z;
        if (p3 < CAP) g_col[d4.w * CAP + p3] = s4.w;
    } else {
        for (int e = e0; e < n_edges; e++) {
            int d = __ldg(dst + e);
            int s = __ldg(src + e);
            int p = atomicAdd(&g_cnt[d], 1);
            if (p < CAP) g_col[d * CAP + p] = s;
        }
    }
}

// ---------------------------------------------------------------------------
// 3) gather (fp16 rows): one warp per node; fp32 accumulate; write fp16 h row.
// ---------------------------------------------------------------------------
__device__ __forceinline__ void acc_half4(float4& acc, uint2 v) {
    float2 lo = __half22float2(*reinterpret_cast<__half2*>(&v.x));
    float2 hi = __half22float2(*reinterpret_cast<__half2*>(&v.y));
    acc.x += lo.x; acc.y += lo.y; acc.z += hi.x; acc.w += hi.y;
}

__global__ void __launch_bounds__(256) gather_kernel() {
    int node = (blockIdx.x * blockDim.x + threadIdx.x) >> 5;
    int lane = threadIdx.x & 31;
    if (node >= NNODES) return;

    int cnt = g_cnt[node];
    if (cnt > CAP) cnt = CAP;
    const int* col = g_col + node * CAP;
    const uint2* f = reinterpret_cast<const uint2*>(g_f16);

    float4 acc = make_float4(0.f, 0.f, 0.f, 0.f);
    int j = 0;
    for (; j + 32 <= cnt; j += 32) {
        int idx = __ldg(col + j + lane);
#pragma unroll
        for (int k = 0; k < 32; k += 8) {
            int s0 = __shfl_sync(0xffffffffu, idx, k);
            int s1 = __shfl_sync(0xffffffffu, idx, k + 1);
            int s2 = __shfl_sync(0xffffffffu, idx, k + 2);
            int s3 = __shfl_sync(0xffffffffu, idx, k + 3);
            int s4 = __shfl_sync(0xffffffffu, idx, k + 4);
            int s5 = __shfl_sync(0xffffffffu, idx, k + 5);
            int s6 = __shfl_sync(0xffffffffu, idx, k + 6);
            int s7 = __shfl_sync(0xffffffffu, idx, k + 7);
            uint2 v0 = __ldg(f + s0 * 32 + lane);
            uint2 v1 = __ldg(f + s1 * 32 + lane);
            uint2 v2 = __ldg(f + s2 * 32 + lane);
            uint2 v3 = __ldg(f + s3 * 32 + lane);
            uint2 v4 = __ldg(f + s4 * 32 + lane);
            uint2 v5 = __ldg(f + s5 * 32 + lane);
            uint2 v6 = __ldg(f + s6 * 32 + lane);
            uint2 v7 = __ldg(f + s7 * 32 + lane);
            acc_half4(acc, v0); acc_half4(acc, v1);
            acc_half4(acc, v2); acc_half4(acc, v3);
            acc_half4(acc, v4); acc_half4(acc, v5);
            acc_half4(acc, v6); acc_half4(acc, v7);
        }
    }
    if (j < cnt) {
        int rem = cnt - j;
        int idx = (lane < rem) ? __ldg(col + j + lane) : 0;
        for (int k = 0; k < rem; k++) {
            int s = __shfl_sync(0xffffffffu, idx, k);
            uint2 v = __ldg(f + s * 32 + lane);
            acc_half4(acc, v);
        }
    }
    __half2 h01 = __floats2half2_rn(acc.x, acc.y);
    __half2 h23 = __floats2half2_rn(acc.z, acc.w);
    uint2 o;
    o.x = *reinterpret_cast<uint32_t*>(&h01);
    o.y = *reinterpret_cast<uint32_t*>(&h23);
    reinterpret_cast<uint2*>(g_h16)[node * 32 + lane] = o;
}

// ---------------------------------------------------------------------------
// 4) out = h @ W + b. fp16 mma m16n8k16, fp32 accum, ldmatrix fragments.
//    Block tile 64(M)x64(N), KC=32, 3-stage cp.async ring, one sync/iter.
//    8 warps = 4(M) x 2(N), warp tile 16x32. Grid 158x4 = 632 blocks
//    (~4.3/SM — fixes the grid-limited 2.1 blocks/SM of the 128x64 tile).
//    Final iteration uses wait_group 0 (round-9 race fix — load-bearing).
// ---------------------------------------------------------------------------
#define KC 32
#define SA_STR 40
#define SB_STR 72
#define NITER (INF / KC)

__device__ __forceinline__ void cpa16(uint32_t dst, const void* src, int sz) {
    asm volatile("cp.async.cg.shared.global [%0], [%1], 16, %2;"
                 :: "r"(dst), "l"(src), "r"(sz) : "memory");
}
#define LDSM_X4(r0, r1, r2, r3, addr)                                        \
    asm volatile("ldmatrix.sync.aligned.m8n8.x4.shared.b16 {%0,%1,%2,%3}, [%4];" \
                 : "=r"(r0), "=r"(r1), "=r"(r2), "=r"(r3) : "r"(addr))
#define LDSM_X4_T(r0, r1, r2, r3, addr)                                      \
    asm volatile("ldmatrix.sync.aligned.m8n8.x4.trans.shared.b16 {%0,%1,%2,%3}, [%4];" \
                 : "=r"(r0), "=r"(r1), "=r"(r2), "=r"(r3) : "r"(addr))

__global__ void __launch_bounds__(256) gemm_tc_kernel(
    const float* __restrict__ bias,
    float* __restrict__ out)
{
    __shared__ __half sa[3][64 * SA_STR];
    __shared__ __half sb[3][KC * SB_STR];

    int t    = threadIdx.x;
    int warp = t >> 5;
    int lane = t & 31;
    int gid  = lane >> 2;
    int tig  = lane & 3;

    int m0 = blockIdx.x * 64;
    int n0 = blockIdx.y * 64;
    int wm = (warp & 3) * 16;    // 4 warps along M, 16 rows each
    int wn = (warp >> 2) * 32;   // 2 warps along N, 32 cols each

    uint32_t sa_base = (uint32_t)__cvta_generic_to_shared(&sa[0][0]);
    uint32_t sb_base = (uint32_t)__cvta_generic_to_shared(&sb[0][0]);

    // cp.async slots. A: 256 chunks/stage (64 rows x 4), 1/thread.
    //                 B: 256 chunks/stage (32 rows x 8), 1/thread.
    int am  = t >> 2;
    int ac8 = t & 3;
    int bkr = t >> 3;
    int bc8 = t & 7;

    // ldmatrix per-lane offsets
    int a_row = (lane & 15);
    int a_col = (lane >> 4) * 8;
    int b_row = (lane & 15);
    int b_col = (lane >> 4) * 8;

    float c[4][4];
#pragma unroll
    for (int nt = 0; nt < 4; nt++)
#pragma unroll
        for (int r = 0; r < 4; r++) c[nt][r] = 0.f;

    auto issue = [&](int st, int kc) {
        int gm = m0 + am;
        int sz = (gm < NNODES) ? 16 : 0;
        cpa16(sa_base + (uint32_t)((st * 64 * SA_STR + am * SA_STR + ac8 * 8) * 2),
              g_h16 + (size_t)gm * INF + kc + ac8 * 8, sz);
        cpa16(sb_base + (uint32_t)((st * KC * SB_STR + bkr * SB_STR + bc8 * 8) * 2),
              g_W16 + (size_t)(kc + bkr) * OUTF + n0 + bc8 * 8, 16);
        asm volatile("cp.async.commit_group;" ::: "memory");
    };

    issue(0, 0);
    issue(1, KC);

#pragma unroll
    for (int it = 0; it < NITER; it++) {
        if (it == NITER - 1)
            asm volatile("cp.async.wait_group 0;" ::: "memory");  // drain last group
        else
            asm volatile("cp.async.wait_group 1;" ::: "memory");
        __syncthreads();
        if (it + 2 < NITER) issue((it + 2) % 3, (it + 2) * KC);

        uint32_t A0 = sa_base + (uint32_t)((it % 3) * 64 * SA_STR * 2);
        uint32_t B0 = sb_base + (uint32_t)((it % 3) * KC * SB_STR * 2);

#pragma unroll
        for (int ks = 0; ks < KC; ks += 16) {
            uint32_t a[4];
            {
                uint32_t addr = A0 + (uint32_t)(((wm + a_row) * SA_STR
                                                 + ks + a_col) * 2);
                LDSM_X4(a[0], a[1], a[2], a[3], addr);
            }
            uint32_t bf[4][2];
#pragma unroll
            for (int np = 0; np < 2; np++) {
                uint32_t r0, r1, r2, r3;
                uint32_t addr = B0 + (uint32_t)(((ks + b_row) * SB_STR
                                                 + wn + np * 16 + b_col) * 2);
                LDSM_X4_T(r0, r1, r2, r3, addr);
                bf[np * 2][0] = r0; bf[np * 2][1] = r1;
                bf[np * 2 + 1][0] = r2; bf[np * 2 + 1][1] = r3;
            }
#pragma unroll
            for (int nt = 0; nt < 4; nt++) {
                asm volatile(
                    "mma.sync.aligned.m16n8k16.row.col.f32.f16.f16.f32 "
                    "{%0,%1,%2,%3}, {%4,%5,%6,%7}, {%8,%9}, {%0,%1,%2,%3};"
                    : "+f"(c[nt][0]), "+f"(c[nt][1]),
                      "+f"(c[nt][2]), "+f"(c[nt][3])
                    : "r"(a[0]), "r"(a[1]), "r"(a[2]), "r"(a[3]),
                      "r"(bf[nt][0]), "r"(bf[nt][1]));
            }
        }
    }

    // Epilogue: bias + store
#pragma unroll
    for (int nt = 0; nt < 4; nt++) {
        int colg = n0 + wn + nt * 8 + tig * 2;
        float2 bv = *reinterpret_cast<const float2*>(bias + colg);
        int row0 = m0 + wm + gid;
        int row1 = row0 + 8;
        if (row0 < NNODES) {
            float2 o = make_float2(c[nt][0] + bv.x, c[nt][1] + bv.y);
            *reinterpret_cast<float2*>(out + (size_t)row0 * OUTF + colg) = o;
        }
        if (row1 < NNODES) {
            float2 o = make_float2(c[nt][2] + bv.x, c[nt][3] + bv.y);
            *reinterpret_cast<float2*>(out + (size_t)row1 * OUTF + colg) = o;
        }
    }
}

// ---------------------------------------------------------------------------
extern "C" void kernel_launch(void* const* d_in, const int* in_sizes, int n_in,
                              void* d_out, int out_size) {
    const float* feature = (const float*)d_in[0];
    const int*   src     = (const int*)d_in[1];
    const int*   dst     = (const int*)d_in[2];
    const float* W       = (const float*)d_in[3];
    const float* b       = (const float*)d_in[4];
    float*       out     = (float*)d_out;

    int n_edges = in_sizes[1];

    int prep_threads = NNODES * INF / 8;   // 160000
    prep_kernel<<<(prep_threads + 255) / 256, 256>>>(feature, W);

    int fill_threads = (n_edges + 3) / 4;
    fill_kernel<<<(fill_threads + 255) / 256, 256>>>(src, dst, n_edges);

    int gather_blocks = (NNODES * 32 + 255) / 256;
    gather_kernel<<<gather_blocks, 256>>>();

    dim3 grid((NNODES + 63) / 64, OUTF / 64);
    gemm_tc_kernel<<<grid, 256>>>(b, out);
}